// round 1
// baseline (speedup 1.0000x reference)
#include <cuda_runtime.h>
#include <math.h>

#define T_TOK   4096
#define DM      768
#define DE      3072
#define N_EXP   8
#define TOPK    2
#define NSLOT   (T_TOK * TOPK)   // 8192

// ---- scratch (device globals; no runtime allocation) ----
__device__ int   g_cnt[N_EXP];
__device__ int   g_fill[N_EXP];
__device__ int   g_off[N_EXP + 1];
__device__ int   g_tok[NSLOT];
__device__ float g_wt[NSLOT];
__device__ float g_h[(size_t)NSLOT * DE];   // 96 MB intermediate h

// ---------------------------------------------------------------------------
// Routing
// ---------------------------------------------------------------------------
__global__ void k_zero_out(float* out) {
    int i = blockIdx.x * 256 + threadIdx.x;
    if (i < T_TOK * DM) out[i] = 0.0f;
    if (blockIdx.x == 0 && threadIdx.x < N_EXP) { g_cnt[threadIdx.x] = 0; g_fill[threadIdx.x] = 0; }
}

__global__ void k_count(const int* __restrict__ eidx) {
    int s = blockIdx.x * 256 + threadIdx.x;
    if (s < NSLOT) atomicAdd(&g_cnt[eidx[s]], 1);
}

__global__ void k_scan() {
    if (threadIdx.x == 0) {
        int a = 0;
        for (int e = 0; e < N_EXP; e++) { g_off[e] = a; a += g_cnt[e]; }
        g_off[N_EXP] = a;
    }
}

__global__ void k_fill(const int* __restrict__ eidx, const float* __restrict__ rw) {
    int s = blockIdx.x * 256 + threadIdx.x;
    if (s < NSLOT) {
        int e = eidx[s];
        int p = g_off[e] + atomicAdd(&g_fill[e], 1);
        g_tok[p] = s / TOPK;
        g_wt[p]  = rw[s];
    }
}

// ---------------------------------------------------------------------------
// Phase 1: h = silu(x @ Wg) * (x @ Wu)   per expert, gathered rows
// 64x64 tile, 256 threads, 4x4 microtile, K-tile 16
// ---------------------------------------------------------------------------
__global__ __launch_bounds__(256) void k_gemm1(const float* __restrict__ x,
                                               const float* __restrict__ wg,
                                               const float* __restrict__ wu) {
    const int e = blockIdx.z;
    const int cnt = g_cnt[e];
    const int row0 = blockIdx.y * 64;
    if (row0 >= cnt) return;
    const int base = g_off[e];
    const int col0 = blockIdx.x * 64;

    __shared__ float As[16][68];  // k-major
    __shared__ float Bg[16][68];
    __shared__ float Bu[16][68];

    const int tid = threadIdx.x;
    const int tx = tid & 15, ty = tid >> 4;
    const int rowL = tid >> 2;            // 0..63, A loader row
    const int kq   = (tid & 3) * 4;       // 0,4,8,12

    float ag[4][4] = {}, au[4][4] = {};

    const int r_load = row0 + rowL;
    const int tokL = (r_load < cnt) ? g_tok[base + r_load] : -1;
    const float* xrow = (tokL >= 0) ? (x + (size_t)tokL * DM) : x;

    const float* wgp = wg + (size_t)e * DM * DE;
    const float* wup = wu + (size_t)e * DM * DE;

    for (int k0 = 0; k0 < DM; k0 += 16) {
        float4 av = (tokL >= 0) ? *(const float4*)(xrow + k0 + kq)
                                : make_float4(0.f, 0.f, 0.f, 0.f);
        float4 bgv = *(const float4*)(wgp + (size_t)(k0 + ty) * DE + col0 + tx * 4);
        float4 buv = *(const float4*)(wup + (size_t)(k0 + ty) * DE + col0 + tx * 4);
        __syncthreads();
        As[kq + 0][rowL] = av.x; As[kq + 1][rowL] = av.y;
        As[kq + 2][rowL] = av.z; As[kq + 3][rowL] = av.w;
        *(float4*)&Bg[ty][tx * 4] = bgv;
        *(float4*)&Bu[ty][tx * 4] = buv;
        __syncthreads();

        #pragma unroll
        for (int kk = 0; kk < 16; kk++) {
            float4 a  = *(const float4*)&As[kk][ty * 4];
            float4 b4 = *(const float4*)&Bg[kk][tx * 4];
            float4 u4 = *(const float4*)&Bu[kk][tx * 4];
            float av_[4] = {a.x, a.y, a.z, a.w};
            float bv_[4] = {b4.x, b4.y, b4.z, b4.w};
            float uv_[4] = {u4.x, u4.y, u4.z, u4.w};
            #pragma unroll
            for (int i = 0; i < 4; i++)
                #pragma unroll
                for (int j = 0; j < 4; j++) {
                    ag[i][j] = fmaf(av_[i], bv_[j], ag[i][j]);
                    au[i][j] = fmaf(av_[i], uv_[j], au[i][j]);
                }
        }
    }

    #pragma unroll
    for (int i = 0; i < 4; i++) {
        int r = row0 + ty * 4 + i;
        if (r >= cnt) continue;
        float* hrow = &g_h[(size_t)(base + r) * DE + col0 + tx * 4];
        #pragma unroll
        for (int j = 0; j < 4; j++) {
            float g = ag[i][j];
            float h = g / (1.0f + expf(-g)) * au[i][j];
            hrow[j] = h;
        }
    }
}

// ---------------------------------------------------------------------------
// Phase 2: out[tok] += (h @ Wd) * wt     (atomicAdd, out pre-zeroed)
// ---------------------------------------------------------------------------
__global__ __launch_bounds__(256) void k_gemm2(const float* __restrict__ wd,
                                               float* __restrict__ out) {
    const int e = blockIdx.z;
    const int cnt = g_cnt[e];
    const int row0 = blockIdx.y * 64;
    if (row0 >= cnt) return;
    const int base = g_off[e];
    const int col0 = blockIdx.x * 64;

    __shared__ float As[16][68];
    __shared__ float Bs[16][68];

    const int tid = threadIdx.x;
    const int tx = tid & 15, ty = tid >> 4;
    const int rowL = tid >> 2;
    const int kq   = (tid & 3) * 4;

    float acc[4][4] = {};

    const int r_load = row0 + rowL;
    const bool rok = (r_load < cnt);
    const float* hrow = rok ? (g_h + (size_t)(base + r_load) * DE) : g_h;
    const float* wdp = wd + (size_t)e * DE * DM;

    for (int k0 = 0; k0 < DE; k0 += 16) {
        float4 av = rok ? *(const float4*)(hrow + k0 + kq)
                        : make_float4(0.f, 0.f, 0.f, 0.f);
        float4 bv = *(const float4*)(wdp + (size_t)(k0 + ty) * DM + col0 + tx * 4);
        __syncthreads();
        As[kq + 0][rowL] = av.x; As[kq + 1][rowL] = av.y;
        As[kq + 2][rowL] = av.z; As[kq + 3][rowL] = av.w;
        *(float4*)&Bs[ty][tx * 4] = bv;
        __syncthreads();

        #pragma unroll
        for (int kk = 0; kk < 16; kk++) {
            float4 a  = *(const float4*)&As[kk][ty * 4];
            float4 b4 = *(const float4*)&Bs[kk][tx * 4];
            float av_[4] = {a.x, a.y, a.z, a.w};
            float bv_[4] = {b4.x, b4.y, b4.z, b4.w};
            #pragma unroll
            for (int i = 0; i < 4; i++)
                #pragma unroll
                for (int j = 0; j < 4; j++)
                    acc[i][j] = fmaf(av_[i], bv_[j], acc[i][j]);
        }
    }

    #pragma unroll
    for (int i = 0; i < 4; i++) {
        int r = row0 + ty * 4 + i;
        if (r >= cnt) continue;
        float w = g_wt[base + r];
        int   t = g_tok[base + r];
        float* orow = out + (size_t)t * DM + col0 + tx * 4;
        #pragma unroll
        for (int j = 0; j < 4; j++)
            atomicAdd(&orow[j], acc[i][j] * w);
    }
}

// ---------------------------------------------------------------------------
extern "C" void kernel_launch(void* const* d_in, const int* in_sizes, int n_in,
                              void* d_out, int out_size) {
    const float* x  = (const float*)d_in[0];
    const float* rw = (const float*)d_in[1];
    const float* wg = (const float*)d_in[2];
    const float* wu = (const float*)d_in[3];
    const float* wd = (const float*)d_in[4];
    const int*   ei = (const int*)d_in[5];
    float* out = (float*)d_out;

    k_zero_out<<<(T_TOK * DM + 255) / 256, 256>>>(out);
    k_count<<<NSLOT / 256, 256>>>(ei);
    k_scan<<<1, 32>>>();
    k_fill<<<NSLOT / 256, 256>>>(ei, rw);

    dim3 g1(DE / 64, NSLOT / 64, N_EXP);   // 48 x 128 x 8
    k_gemm1<<<g1, 256>>>(x, wg, wu);

    dim3 g2(DM / 64, NSLOT / 64, N_EXP);   // 12 x 128 x 8
    k_gemm2<<<g2, 256>>>(wd, out);
}

// round 3
// speedup vs baseline: 3.2385x; 3.2385x over previous
#include <cuda_runtime.h>
#include <math.h>
#include <stdint.h>

#define T_TOK   4096
#define DM      768
#define DE      3072
#define N_EXP   8
#define TOPK    2
#define NSLOT   (T_TOK * TOPK)   // 8192

// ---------------- scratch (device globals) ----------------
__device__ int   g_cnt[N_EXP];
__device__ int   g_fill[N_EXP];
__device__ int   g_off[N_EXP + 1];
__device__ int   g_tok[NSLOT];
__device__ float g_wt[NSLOT];
__device__ __align__(256) float g_h[(size_t)(NSLOT + 160) * DE];   // padded rows

// ---------------- helpers ----------------
__device__ __forceinline__ uint32_t smem_u32(const void* p) {
    uint32_t a;
    asm("{ .reg .u64 t; cvta.to.shared.u64 t, %1; cvt.u32.u64 %0, t; }" : "=r"(a) : "l"(p));
    return a;
}
#define CP16(dst, src) asm volatile("cp.async.cg.shared.global [%0], [%1], 16;" :: "r"(dst), "l"(src))
#define CP_COMMIT()    asm volatile("cp.async.commit_group;" ::: "memory")
#define CP_WAIT1()     asm volatile("cp.async.wait_group 1;" ::: "memory")

__device__ __forceinline__ uint32_t f2tf(float f) {
    uint32_t r; asm("cvt.rna.tf32.f32 %0, %1;" : "=r"(r) : "f"(f)); return r;
}
__device__ __forceinline__ void mma_tf32(float* c, const uint32_t* a, const uint32_t* b) {
    asm volatile("mma.sync.aligned.m16n8k8.row.col.f32.tf32.tf32.f32 "
                 "{%0,%1,%2,%3}, {%4,%5,%6,%7}, {%8,%9}, {%0,%1,%2,%3};"
                 : "+f"(c[0]), "+f"(c[1]), "+f"(c[2]), "+f"(c[3])
                 : "r"(a[0]), "r"(a[1]), "r"(a[2]), "r"(a[3]), "r"(b[0]), "r"(b[1]));
}

// smem float strides (padded for conflict-free fragment loads)
#define AST 36    // A tile row stride (32 k + 4 pad)   -> bank (4g+t), bijective
#define BST 136   // B tile k-row stride (128 n + 8 pad) -> bank (8t+g), bijective
#define A_ST_F (128 * AST)   // 4608 floats / stage
#define B_ST_F (32 * BST)    // 4352 floats / stage

// ---------------- routing ----------------
__global__ void k_zero_out(float* out) {
    int i = blockIdx.x * 256 + threadIdx.x;
    if (i < T_TOK * DM) out[i] = 0.0f;
    if (blockIdx.x == 0 && threadIdx.x < N_EXP) { g_cnt[threadIdx.x] = 0; g_fill[threadIdx.x] = 0; }
}
__global__ void k_count(const int* __restrict__ eidx) {
    int s = blockIdx.x * 256 + threadIdx.x;
    if (s < NSLOT) atomicAdd(&g_cnt[eidx[s]], 1);
}
__global__ void k_scan() {
    if (threadIdx.x == 0) {
        int a = 0;
        for (int e = 0; e < N_EXP; e++) { g_off[e] = a; a += g_cnt[e]; }
        g_off[N_EXP] = a;
    }
}
__global__ void k_fill(const int* __restrict__ eidx, const float* __restrict__ rw) {
    int s = blockIdx.x * 256 + threadIdx.x;
    if (s < NSLOT) {
        int e = eidx[s];
        int p = g_off[e] + atomicAdd(&g_fill[e], 1);
        g_tok[p] = s / TOPK;
        g_wt[p]  = rw[s];
    }
}

// ===========================================================================
// GEMM1: h = silu(x Wg) * (x Wu)  — fused, tf32 mma.sync, 3-stage cp.async
// CTA 128x128x32, 8 warps (2x4), warp tile 64x32
// ===========================================================================
#define NS1 24   // 768/32
#define S1_SMEM ((3 * A_ST_F + 6 * B_ST_F) * 4)   // 159744 B

__global__ __launch_bounds__(256) void k_mma1(const float* __restrict__ x,
                                              const float* __restrict__ wg,
                                              const float* __restrict__ wu) {
    const int e = blockIdx.z;
    const int cnt = g_cnt[e];
    const int row0 = blockIdx.y * 128;
    if (row0 >= cnt) return;
    const int base = g_off[e];
    const int col0 = blockIdx.x * 128;

    extern __shared__ float smf[];
    const uint32_t sa = smem_u32(smf);
    // float offsets: A[3] then G[3] then U[3]
    const int G0 = 3 * A_ST_F;            // 13824
    const int U0 = G0 + 3 * B_ST_F;       // 26880

    const int tid = threadIdx.x;
    const int wid = tid >> 5, lid = tid & 31;
    const int wm = wid >> 2, wn = wid & 3;       // warp grid 2x4
    const int g = lid >> 2, t = lid & 3;

    // ---- loader geometry ----
    const int rowA = tid >> 3, chA = tid & 7;        // A: 128 rows x 8 chunks(16B)
    const int rowB = tid >> 5, chB = tid & 31;       // B: 32 k-rows x 32 chunks(16B)

    const char* pA[4];
    #pragma unroll
    for (int j = 0; j < 4; j++) {
        int rr = row0 + rowA + 32 * j;
        int idx = base + (rr < cnt ? rr : cnt - 1);
        pA[j] = (const char*)(x + (size_t)g_tok[idx] * DM) + chA * 16;
    }
    const char* pG = (const char*)(wg + ((size_t)e * DM + rowB) * DE + col0) + chB * 16;
    const char* pU = (const char*)(wu + ((size_t)e * DM + rowB) * DE + col0) + chB * 16;
    const size_t bStride = (size_t)32 * DE * 4;      // bytes per BK stage
    uint32_t aOff[4], bOff[4];
    #pragma unroll
    for (int j = 0; j < 4; j++) {
        aOff[j] = (uint32_t)(((rowA + 32 * j) * AST + chA * 4) * 4);
        bOff[j] = (uint32_t)(((rowB + 8 * j) * BST + chB * 4) * 4);
    }

#define LOAD1(buf) do {                                                        \
        uint32_t a_s = sa + (uint32_t)((buf) * A_ST_F * 4);                    \
        uint32_t g_s = sa + (uint32_t)((G0 + (buf) * B_ST_F) * 4);             \
        uint32_t u_s = sa + (uint32_t)((U0 + (buf) * B_ST_F) * 4);             \
        _Pragma("unroll") for (int j = 0; j < 4; j++) {                        \
            CP16(a_s + aOff[j], pA[j]); pA[j] += 128;                          \
            CP16(g_s + bOff[j], pG + (size_t)(8 * j) * DE * 4);                \
            CP16(u_s + bOff[j], pU + (size_t)(8 * j) * DE * 4);                \
        }                                                                      \
        pG += bStride; pU += bStride; } while (0)

    float accG[4][4][4] = {}, accU[4][4][4] = {};

    LOAD1(0); CP_COMMIT();
    LOAD1(1); CP_COMMIT();

    for (int s = 0; s < NS1; s++) {
        CP_WAIT1();
        __syncthreads();
        if (s + 2 < NS1) LOAD1((s + 2) % 3);
        CP_COMMIT();

        const float* As = smf + (s % 3) * A_ST_F;
        const float* Gs = smf + G0 + (s % 3) * B_ST_F;
        const float* Us = smf + U0 + (s % 3) * B_ST_F;

        #pragma unroll
        for (int kst = 0; kst < 4; kst++) {
            const int kb = kst * 8;
            uint32_t afr[4][4];
            #pragma unroll
            for (int mi = 0; mi < 4; mi++) {
                int row = wm * 64 + mi * 16 + g;
                afr[mi][0] = f2tf(As[row * AST + kb + t]);
                afr[mi][1] = f2tf(As[(row + 8) * AST + kb + t]);
                afr[mi][2] = f2tf(As[row * AST + kb + t + 4]);
                afr[mi][3] = f2tf(As[(row + 8) * AST + kb + t + 4]);
            }
            uint32_t bg[4][2], bu[4][2];
            #pragma unroll
            for (int ni = 0; ni < 4; ni++) {
                int col = wn * 32 + ni * 8 + g;
                bg[ni][0] = f2tf(Gs[(kb + t) * BST + col]);
                bg[ni][1] = f2tf(Gs[(kb + t + 4) * BST + col]);
                bu[ni][0] = f2tf(Us[(kb + t) * BST + col]);
                bu[ni][1] = f2tf(Us[(kb + t + 4) * BST + col]);
            }
            #pragma unroll
            for (int mi = 0; mi < 4; mi++)
                #pragma unroll
                for (int ni = 0; ni < 4; ni++) {
                    mma_tf32(accG[mi][ni], afr[mi], bg[ni]);
                    mma_tf32(accU[mi][ni], afr[mi], bu[ni]);
                }
        }
        __syncthreads();
    }

    // ---- epilogue: silu(g)*u -> g_h ----
    #pragma unroll
    for (int mi = 0; mi < 4; mi++) {
        #pragma unroll
        for (int hh = 0; hh < 2; hh++) {
            int rl = wm * 64 + mi * 16 + g + 8 * hh;
            int r = row0 + rl;
            if (r >= cnt) continue;
            float* hrow = g_h + (size_t)(base + r) * DE + col0;
            #pragma unroll
            for (int ni = 0; ni < 4; ni++) {
                int col = wn * 32 + ni * 8 + 2 * t;
                float gv0 = accG[mi][ni][2 * hh], gv1 = accG[mi][ni][2 * hh + 1];
                float uv0 = accU[mi][ni][2 * hh], uv1 = accU[mi][ni][2 * hh + 1];
                float2 hv;
                hv.x = gv0 * uv0 / (1.0f + __expf(-gv0));
                hv.y = gv1 * uv1 / (1.0f + __expf(-gv1));
                *(float2*)(hrow + col) = hv;
            }
        }
    }
}

// ===========================================================================
// GEMM2: out += (h Wd) * wt
// ===========================================================================
#define NS2 96   // 3072/32
#define S2_SMEM ((3 * A_ST_F + 3 * B_ST_F) * 4)   // 107520 B

__global__ __launch_bounds__(256) void k_mma2(const float* __restrict__ wd,
                                              float* __restrict__ out) {
    const int e = blockIdx.z;
    const int cnt = g_cnt[e];
    const int row0 = blockIdx.y * 128;
    if (row0 >= cnt) return;
    const int base = g_off[e];
    const int col0 = blockIdx.x * 128;

    extern __shared__ float smf[];
    const uint32_t sa = smem_u32(smf);
    const int B0 = 3 * A_ST_F;

    const int tid = threadIdx.x;
    const int wid = tid >> 5, lid = tid & 31;
    const int wm = wid >> 2, wn = wid & 3;
    const int g = lid >> 2, t = lid & 3;

    const int rowA = tid >> 3, chA = tid & 7;
    const int rowB = tid >> 5, chB = tid & 31;

    const char* pA[4];
    #pragma unroll
    for (int j = 0; j < 4; j++)
        pA[j] = (const char*)(g_h + (size_t)(base + row0 + rowA + 32 * j) * DE) + chA * 16;
    const char* pB = (const char*)(wd + ((size_t)e * DE + rowB) * DM + col0) + chB * 16;
    const size_t bStride = (size_t)32 * DM * 4;
    uint32_t aOff[4], bOff[4];
    #pragma unroll
    for (int j = 0; j < 4; j++) {
        aOff[j] = (uint32_t)(((rowA + 32 * j) * AST + chA * 4) * 4);
        bOff[j] = (uint32_t)(((rowB + 8 * j) * BST + chB * 4) * 4);
    }

#define LOAD2(buf) do {                                                        \
        uint32_t a_s = sa + (uint32_t)((buf) * A_ST_F * 4);                    \
        uint32_t b_s = sa + (uint32_t)((B0 + (buf) * B_ST_F) * 4);             \
        _Pragma("unroll") for (int j = 0; j < 4; j++) {                        \
            CP16(a_s + aOff[j], pA[j]); pA[j] += 128;                          \
            CP16(b_s + bOff[j], pB + (size_t)(8 * j) * DM * 4);                \
        }                                                                      \
        pB += bStride; } while (0)

    float acc[4][4][4] = {};

    LOAD2(0); CP_COMMIT();
    LOAD2(1); CP_COMMIT();

    for (int s = 0; s < NS2; s++) {
        CP_WAIT1();
        __syncthreads();
        if (s + 2 < NS2) LOAD2((s + 2) % 3);
        CP_COMMIT();

        const float* As = smf + (s % 3) * A_ST_F;
        const float* Bs = smf + B0 + (s % 3) * B_ST_F;

        #pragma unroll
        for (int kst = 0; kst < 4; kst++) {
            const int kb = kst * 8;
            uint32_t afr[4][4];
            #pragma unroll
            for (int mi = 0; mi < 4; mi++) {
                int row = wm * 64 + mi * 16 + g;
                afr[mi][0] = f2tf(As[row * AST + kb + t]);
                afr[mi][1] = f2tf(As[(row + 8) * AST + kb + t]);
                afr[mi][2] = f2tf(As[row * AST + kb + t + 4]);
                afr[mi][3] = f2tf(As[(row + 8) * AST + kb + t + 4]);
            }
            uint32_t bfr[4][2];
            #pragma unroll
            for (int ni = 0; ni < 4; ni++) {
                int col = wn * 32 + ni * 8 + g;
                bfr[ni][0] = f2tf(Bs[(kb + t) * BST + col]);
                bfr[ni][1] = f2tf(Bs[(kb + t + 4) * BST + col]);
            }
            #pragma unroll
            for (int mi = 0; mi < 4; mi++)
                #pragma unroll
                for (int ni = 0; ni < 4; ni++)
                    mma_tf32(acc[mi][ni], afr[mi], bfr[ni]);
        }
        __syncthreads();
    }

    // ---- epilogue: weighted atomic accumulation ----
    #pragma unroll
    for (int mi = 0; mi < 4; mi++) {
        #pragma unroll
        for (int hh = 0; hh < 2; hh++) {
            int rl = wm * 64 + mi * 16 + g + 8 * hh;
            int r = row0 + rl;
            if (r >= cnt) continue;
            float w = g_wt[base + r];
            float* orow = out + (size_t)g_tok[base + r] * DM + col0;
            #pragma unroll
            for (int ni = 0; ni < 4; ni++) {
                int col = wn * 32 + ni * 8 + 2 * t;
                atomicAdd(&orow[col],     acc[mi][ni][2 * hh]     * w);
                atomicAdd(&orow[col + 1], acc[mi][ni][2 * hh + 1] * w);
            }
        }
    }
}

// ---------------------------------------------------------------------------
extern "C" void kernel_launch(void* const* d_in, const int* in_sizes, int n_in,
                              void* d_out, int out_size) {
    const float* x  = (const float*)d_in[0];
    const float* rw = (const float*)d_in[1];
    const float* wg = (const float*)d_in[2];
    const float* wu = (const float*)d_in[3];
    const float* wd = (const float*)d_in[4];
    const int*   ei = (const int*)d_in[5];
    float* out = (float*)d_out;

    static bool attr_done = false;
    if (!attr_done) {
        cudaFuncSetAttribute(k_mma1, cudaFuncAttributeMaxDynamicSharedMemorySize, S1_SMEM);
        cudaFuncSetAttribute(k_mma2, cudaFuncAttributeMaxDynamicSharedMemorySize, S2_SMEM);
        attr_done = true;
    }

    k_zero_out<<<(T_TOK * DM + 255) / 256, 256>>>(out);
    k_count<<<NSLOT / 256, 256>>>(ei);
    k_scan<<<1, 32>>>();
    k_fill<<<NSLOT / 256, 256>>>(ei, rw);

    dim3 g1(DE / 128, NSLOT / 128, N_EXP);   // 24 x 64 x 8
    k_mma1<<<g1, 256, S1_SMEM>>>(x, wg, wu);

    dim3 g2(DM / 128, NSLOT / 128, N_EXP);   // 6 x 64 x 8
    k_mma2<<<g2, 256, S2_SMEM>>>(wd, out);
}

// round 4
// speedup vs baseline: 5.0394x; 1.5561x over previous
#include <cuda_runtime.h>
#include <cuda_fp16.h>
#include <math.h>
#include <stdint.h>

#define T_TOK   4096
#define DM      768
#define DE      3072
#define N_EXP   8
#define TOPK    2
#define NSLOT   (T_TOK * TOPK)   // 8192

// ---------------- scratch ----------------
__device__ int    g_cnt[N_EXP];
__device__ int    g_fill[N_EXP];
__device__ int    g_off[N_EXP + 1];
__device__ int    g_tok[NSLOT];
__device__ float  g_wt[NSLOT];
__device__ __align__(256) __half g_xH[(size_t)T_TOK * DM];
__device__ __align__(256) __half g_wgH[(size_t)N_EXP * DM * DE];
__device__ __align__(256) __half g_wuH[(size_t)N_EXP * DM * DE];
__device__ __align__(256) __half g_wdH[(size_t)N_EXP * DE * DM];
__device__ __align__(256) __half g_hH[(size_t)(NSLOT + 160) * DE];

// ---------------- helpers ----------------
__device__ __forceinline__ uint32_t smem_u32(const void* p) {
    uint32_t a;
    asm("{ .reg .u64 t; cvta.to.shared.u64 t, %1; cvt.u32.u64 %0, t; }" : "=r"(a) : "l"(p));
    return a;
}
#define CP16(dst, src) asm volatile("cp.async.cg.shared.global [%0], [%1], 16;" :: "r"(dst), "l"(src))
#define CP_COMMIT()    asm volatile("cp.async.commit_group;" ::: "memory")
#define CP_WAIT1()     asm volatile("cp.async.wait_group 1;" ::: "memory")

#define LDSM_X4(r0, r1, r2, r3, a) \
    asm volatile("ldmatrix.sync.aligned.m8n8.x4.shared.b16 {%0,%1,%2,%3}, [%4];" \
                 : "=r"(r0), "=r"(r1), "=r"(r2), "=r"(r3) : "r"(a))
#define LDSM_X4T(r0, r1, r2, r3, a) \
    asm volatile("ldmatrix.sync.aligned.m8n8.x4.trans.shared.b16 {%0,%1,%2,%3}, [%4];" \
                 : "=r"(r0), "=r"(r1), "=r"(r2), "=r"(r3) : "r"(a))

__device__ __forceinline__ void mma_f16(float* c, const uint32_t* a, const uint32_t* b) {
    asm volatile("mma.sync.aligned.m16n8k16.row.col.f32.f16.f16.f32 "
                 "{%0,%1,%2,%3}, {%4,%5,%6,%7}, {%8,%9}, {%0,%1,%2,%3};"
                 : "+f"(c[0]), "+f"(c[1]), "+f"(c[2]), "+f"(c[3])
                 : "r"(a[0]), "r"(a[1]), "r"(a[2]), "r"(a[3]), "r"(b[0]), "r"(b[1]));
}

// padded smem strides (bytes) — conflict-free ldmatrix phases
#define A_STRIDE 80      // 32 halves (64B) + 16B pad : banks 20r mod 32 distinct
#define B_STRIDE 272     // 128 halves (256B) + 16B pad: banks 4k mod 32 distinct
#define A_BYTES  (128 * A_STRIDE)   // 10240
#define B_BYTES  (32 * B_STRIDE)    // 8704

// ---------------- routing ----------------
__global__ void k_zero_out(float* out) {
    int i = blockIdx.x * 256 + threadIdx.x;
    if (i < T_TOK * DM) out[i] = 0.0f;
    if (blockIdx.x == 0 && threadIdx.x < N_EXP) { g_cnt[threadIdx.x] = 0; g_fill[threadIdx.x] = 0; }
}
__global__ void k_count(const int* __restrict__ eidx) {
    int s = blockIdx.x * 256 + threadIdx.x;
    if (s < NSLOT) atomicAdd(&g_cnt[eidx[s]], 1);
}
__global__ void k_scan() {
    if (threadIdx.x == 0) {
        int a = 0;
        for (int e = 0; e < N_EXP; e++) { g_off[e] = a; a += g_cnt[e]; }
        g_off[N_EXP] = a;
    }
}
__global__ void k_fill(const int* __restrict__ eidx, const float* __restrict__ rw) {
    int s = blockIdx.x * 256 + threadIdx.x;
    if (s < NSLOT) {
        int e = eidx[s];
        int p = g_off[e] + atomicAdd(&g_fill[e], 1);
        g_tok[p] = s / TOPK;
        g_wt[p]  = rw[s];
    }
}

// ---------------- fp32 -> fp16 convert ----------------
__global__ __launch_bounds__(256) void k_cvt(const float* __restrict__ s,
                                             __half* __restrict__ d, int n) {
    int i = (blockIdx.x * 256 + threadIdx.x) * 4;
    if (i < n) {
        float4 v = *(const float4*)(s + i);
        *(__half2*)(d + i)     = __floats2half2_rn(v.x, v.y);
        *(__half2*)(d + i + 2) = __floats2half2_rn(v.z, v.w);
    }
}

// ===========================================================================
// GEMM1: h = silu(x Wg) * (x Wu) — fp16 mma.sync, ldmatrix, 3-stage cp.async
// CTA 128x128x32, 8 warps (2x4), warp tile 64x32
// ===========================================================================
#define STG1 (A_BYTES + 2 * B_BYTES)   // 27648
#define S1_SMEM (3 * STG1)             // 82944
#define NS1 24                         // 768/32

__global__ __launch_bounds__(256) void k_mma1() {
    const int e = blockIdx.z;
    const int cnt = g_cnt[e];
    const int row0 = blockIdx.y * 128;
    if (row0 >= cnt) return;
    const int base = g_off[e];
    const int col0 = blockIdx.x * 128;

    extern __shared__ char sm[];
    const uint32_t sa = smem_u32(sm);

    const int tid = threadIdx.x;
    const int wid = tid >> 5, lid = tid & 31;
    const int wm = wid >> 2, wn = wid & 3;
    const int g = lid >> 2, t = lid & 3;
    const int lidlo = lid & 15, lidhi = lid >> 4;

    // ---- loader geometry (2 tasks per thread per array) ----
    uint32_t aoff[2], boff[2];
    const char* pA[2]; const char* pG[2]; const char* pU[2];
    #pragma unroll
    for (int j = 0; j < 2; j++) {
        int task = tid + 256 * j;
        int ar = task >> 2, ac = task & 3;           // A: 128 rows x 4 chunks
        int rr = row0 + ar;
        int idx = base + (rr < cnt ? rr : cnt - 1);
        pA[j] = (const char*)(g_xH + (size_t)g_tok[idx] * DM) + ac * 16;
        aoff[j] = (uint32_t)(ar * A_STRIDE + ac * 16);
        int br = task >> 4, bc = task & 15;          // B: 32 k-rows x 16 chunks
        pG[j] = (const char*)(g_wgH + ((size_t)e * DM + br) * DE + col0) + bc * 16;
        pU[j] = (const char*)(g_wuH + ((size_t)e * DM + br) * DE + col0) + bc * 16;
        boff[j] = (uint32_t)(br * B_STRIDE + bc * 16);
    }
    const size_t bAdv = (size_t)32 * DE * 2;

#define LOAD1(buf) do {                                                        \
        uint32_t ab = sa + (uint32_t)((buf) * STG1);                           \
        uint32_t gb = ab + A_BYTES, ub = gb + B_BYTES;                         \
        _Pragma("unroll") for (int j = 0; j < 2; j++) {                        \
            CP16(ab + aoff[j], pA[j]); pA[j] += 64;                            \
            CP16(gb + boff[j], pG[j]); CP16(ub + boff[j], pU[j]);              \
            pG[j] += bAdv; pU[j] += bAdv; } } while (0)

    float accG[4][4][4] = {}, accU[4][4][4] = {};

    LOAD1(0); CP_COMMIT();
    LOAD1(1); CP_COMMIT();

    for (int s = 0; s < NS1; s++) {
        CP_WAIT1();
        __syncthreads();
        if (s + 2 < NS1) LOAD1((s + 2) % 3);
        CP_COMMIT();

        const uint32_t ab = sa + (uint32_t)((s % 3) * STG1);
        const uint32_t gb = ab + A_BYTES, ub = gb + B_BYTES;

        #pragma unroll
        for (int kst = 0; kst < 2; kst++) {
            uint32_t a[4][4], bg[4][2], bu[4][2];
            #pragma unroll
            for (int mi = 0; mi < 4; mi++) {
                uint32_t addr = ab + (uint32_t)((wm * 64 + mi * 16 + lidlo) * A_STRIDE
                                                + (kst * 16 + 8 * lidhi) * 2);
                LDSM_X4(a[mi][0], a[mi][1], a[mi][2], a[mi][3], addr);
            }
            #pragma unroll
            for (int nh = 0; nh < 2; nh++) {
                uint32_t co = (uint32_t)((wn * 32 + nh * 16 + 8 * lidhi) * 2);
                uint32_t ro = (uint32_t)((kst * 16 + lidlo) * B_STRIDE);
                LDSM_X4T(bg[2 * nh][0], bg[2 * nh][1], bg[2 * nh + 1][0], bg[2 * nh + 1][1],
                         gb + ro + co);
                LDSM_X4T(bu[2 * nh][0], bu[2 * nh][1], bu[2 * nh + 1][0], bu[2 * nh + 1][1],
                         ub + ro + co);
            }
            #pragma unroll
            for (int mi = 0; mi < 4; mi++)
                #pragma unroll
                for (int ni = 0; ni < 4; ni++) {
                    mma_f16(accG[mi][ni], a[mi], bg[ni]);
                    mma_f16(accU[mi][ni], a[mi], bu[ni]);
                }
        }
        __syncthreads();
    }

    // ---- epilogue: silu(g)*u -> g_hH (fp16) ----
    #pragma unroll
    for (int mi = 0; mi < 4; mi++) {
        #pragma unroll
        for (int hh = 0; hh < 2; hh++) {
            int r = row0 + wm * 64 + mi * 16 + g + 8 * hh;
            if (r >= cnt) continue;
            __half* hrow = g_hH + (size_t)(base + r) * DE + col0;
            #pragma unroll
            for (int ni = 0; ni < 4; ni++) {
                int col = wn * 32 + ni * 8 + 2 * t;
                float gv0 = accG[mi][ni][2 * hh], gv1 = accG[mi][ni][2 * hh + 1];
                float uv0 = accU[mi][ni][2 * hh], uv1 = accU[mi][ni][2 * hh + 1];
                float h0 = gv0 * uv0 / (1.0f + __expf(-gv0));
                float h1 = gv1 * uv1 / (1.0f + __expf(-gv1));
                *(__half2*)(hrow + col) = __floats2half2_rn(h0, h1);
            }
        }
    }
}

// ===========================================================================
// GEMM2: out += (h Wd) * wt
// ===========================================================================
#define STG2 (A_BYTES + B_BYTES)    // 18944
#define S2_SMEM (3 * STG2)          // 56832
#define NS2 96                      // 3072/32

__global__ __launch_bounds__(256) void k_mma2(float* __restrict__ out) {
    const int e = blockIdx.z;
    const int cnt = g_cnt[e];
    const int row0 = blockIdx.y * 128;
    if (row0 >= cnt) return;
    const int base = g_off[e];
    const int col0 = blockIdx.x * 128;

    extern __shared__ char sm[];
    const uint32_t sa = smem_u32(sm);

    const int tid = threadIdx.x;
    const int wid = tid >> 5, lid = tid & 31;
    const int wm = wid >> 2, wn = wid & 3;
    const int g = lid >> 2, t = lid & 3;
    const int lidlo = lid & 15, lidhi = lid >> 4;

    uint32_t aoff[2], boff[2];
    const char* pA[2]; const char* pB[2];
    #pragma unroll
    for (int j = 0; j < 2; j++) {
        int task = tid + 256 * j;
        int ar = task >> 2, ac = task & 3;
        pA[j] = (const char*)(g_hH + (size_t)(base + row0 + ar) * DE) + ac * 16;
        aoff[j] = (uint32_t)(ar * A_STRIDE + ac * 16);
        int br = task >> 4, bc = task & 15;
        pB[j] = (const char*)(g_wdH + ((size_t)e * DE + br) * DM + col0) + bc * 16;
        boff[j] = (uint32_t)(br * B_STRIDE + bc * 16);
    }
    const size_t bAdv = (size_t)32 * DM * 2;

#define LOAD2(buf) do {                                                        \
        uint32_t ab = sa + (uint32_t)((buf) * STG2);                           \
        uint32_t bb = ab + A_BYTES;                                            \
        _Pragma("unroll") for (int j = 0; j < 2; j++) {                        \
            CP16(ab + aoff[j], pA[j]); pA[j] += 64;                            \
            CP16(bb + boff[j], pB[j]); pB[j] += bAdv; } } while (0)

    float acc[4][4][4] = {};

    LOAD2(0); CP_COMMIT();
    LOAD2(1); CP_COMMIT();

    for (int s = 0; s < NS2; s++) {
        CP_WAIT1();
        __syncthreads();
        if (s + 2 < NS2) LOAD2((s + 2) % 3);
        CP_COMMIT();

        const uint32_t ab = sa + (uint32_t)((s % 3) * STG2);
        const uint32_t bb = ab + A_BYTES;

        #pragma unroll
        for (int kst = 0; kst < 2; kst++) {
            uint32_t a[4][4], bf[4][2];
            #pragma unroll
            for (int mi = 0; mi < 4; mi++) {
                uint32_t addr = ab + (uint32_t)((wm * 64 + mi * 16 + lidlo) * A_STRIDE
                                                + (kst * 16 + 8 * lidhi) * 2);
                LDSM_X4(a[mi][0], a[mi][1], a[mi][2], a[mi][3], addr);
            }
            #pragma unroll
            for (int nh = 0; nh < 2; nh++) {
                uint32_t co = (uint32_t)((wn * 32 + nh * 16 + 8 * lidhi) * 2);
                uint32_t ro = (uint32_t)((kst * 16 + lidlo) * B_STRIDE);
                LDSM_X4T(bf[2 * nh][0], bf[2 * nh][1], bf[2 * nh + 1][0], bf[2 * nh + 1][1],
                         bb + ro + co);
            }
            #pragma unroll
            for (int mi = 0; mi < 4; mi++)
                #pragma unroll
                for (int ni = 0; ni < 4; ni++)
                    mma_f16(acc[mi][ni], a[mi], bf[ni]);
        }
        __syncthreads();
    }

    #pragma unroll
    for (int mi = 0; mi < 4; mi++) {
        #pragma unroll
        for (int hh = 0; hh < 2; hh++) {
            int r = row0 + wm * 64 + mi * 16 + g + 8 * hh;
            if (r >= cnt) continue;
            float w = g_wt[base + r];
            float* orow = out + (size_t)g_tok[base + r] * DM + col0;
            #pragma unroll
            for (int ni = 0; ni < 4; ni++) {
                int col = wn * 32 + ni * 8 + 2 * t;
                atomicAdd(&orow[col],     acc[mi][ni][2 * hh]     * w);
                atomicAdd(&orow[col + 1], acc[mi][ni][2 * hh + 1] * w);
            }
        }
    }
}

// ---------------------------------------------------------------------------
extern "C" void kernel_launch(void* const* d_in, const int* in_sizes, int n_in,
                              void* d_out, int out_size) {
    const float* x  = (const float*)d_in[0];
    const float* rw = (const float*)d_in[1];
    const float* wg = (const float*)d_in[2];
    const float* wu = (const float*)d_in[3];
    const float* wd = (const float*)d_in[4];
    const int*   ei = (const int*)d_in[5];
    float* out = (float*)d_out;

    static bool attr_done = false;
    if (!attr_done) {
        cudaFuncSetAttribute(k_mma1, cudaFuncAttributeMaxDynamicSharedMemorySize, S1_SMEM);
        cudaFuncSetAttribute(k_mma2, cudaFuncAttributeMaxDynamicSharedMemorySize, S2_SMEM);
        attr_done = true;
    }

    __half *xH, *wgH, *wuH, *wdH;
    cudaGetSymbolAddress((void**)&xH,  g_xH);
    cudaGetSymbolAddress((void**)&wgH, g_wgH);
    cudaGetSymbolAddress((void**)&wuH, g_wuH);
    cudaGetSymbolAddress((void**)&wdH, g_wdH);

    k_zero_out<<<(T_TOK * DM + 255) / 256, 256>>>(out);
    k_count<<<NSLOT / 256, 256>>>(ei);
    k_scan<<<1, 32>>>();
    k_fill<<<NSLOT / 256, 256>>>(ei, rw);

    const int NW = N_EXP * DM * DE;             // 18874368
    k_cvt<<<NW / 1024, 256>>>(wg, wgH, NW);
    k_cvt<<<NW / 1024, 256>>>(wu, wuH, NW);
    k_cvt<<<NW / 1024, 256>>>(wd, wdH, NW);
    k_cvt<<<(T_TOK * DM) / 1024, 256>>>(x, xH, T_TOK * DM);

    dim3 g1(DE / 128, NSLOT / 128, N_EXP);   // 24 x 64 x 8
    k_mma1<<<g1, 256, S1_SMEM>>>();

    dim3 g2(DM / 128, NSLOT / 128, N_EXP);   // 6 x 64 x 8
    k_mma2<<<g2, 256, S2_SMEM>>>(out);
}

// round 5
// speedup vs baseline: 5.3702x; 1.0657x over previous
#include <cuda_runtime.h>
#include <cuda_fp16.h>
#include <math.h>
#include <stdint.h>

#define T_TOK   4096
#define DM      768
#define DE      3072
#define N_EXP   8
#define TOPK    2
#define NSLOT   (T_TOK * TOPK)   // 8192
#define MAXTILE 72               // <= 64 full + 8 partial row-tiles

// ---------------- scratch ----------------
__device__ int    g_cnt[N_EXP];
__device__ int    g_fill[N_EXP];
__device__ int    g_off[N_EXP + 1];
__device__ int    g_tok[NSLOT];
__device__ float  g_wt[NSLOT];
__device__ int    g_ntiles;
__device__ int2   g_tile[MAXTILE];
__device__ __align__(256) __half g_xH[(size_t)T_TOK * DM];
__device__ __align__(256) __half g_wgH[(size_t)N_EXP * DM * DE];
__device__ __align__(256) __half g_wuH[(size_t)N_EXP * DM * DE];
__device__ __align__(256) __half g_wdH[(size_t)N_EXP * DE * DM];
__device__ __align__(256) __half g_hH[(size_t)(NSLOT + 160) * DE];

// ---------------- helpers ----------------
__device__ __forceinline__ uint32_t smem_u32(const void* p) {
    uint32_t a;
    asm("{ .reg .u64 t; cvta.to.shared.u64 t, %1; cvt.u32.u64 %0, t; }" : "=r"(a) : "l"(p));
    return a;
}
#define CP16(dst, src) asm volatile("cp.async.cg.shared.global [%0], [%1], 16;" :: "r"(dst), "l"(src))
#define CP_COMMIT()    asm volatile("cp.async.commit_group;" ::: "memory")
#define CP_WAIT2()     asm volatile("cp.async.wait_group 2;" ::: "memory")

#define LDSM_X4(r0, r1, r2, r3, a) \
    asm volatile("ldmatrix.sync.aligned.m8n8.x4.shared.b16 {%0,%1,%2,%3}, [%4];" \
                 : "=r"(r0), "=r"(r1), "=r"(r2), "=r"(r3) : "r"(a))
#define LDSM_X4T(r0, r1, r2, r3, a) \
    asm volatile("ldmatrix.sync.aligned.m8n8.x4.trans.shared.b16 {%0,%1,%2,%3}, [%4];" \
                 : "=r"(r0), "=r"(r1), "=r"(r2), "=r"(r3) : "r"(a))

__device__ __forceinline__ void mma_f16(float* c, const uint32_t* a, const uint32_t* b) {
    asm volatile("mma.sync.aligned.m16n8k16.row.col.f32.f16.f16.f32 "
                 "{%0,%1,%2,%3}, {%4,%5,%6,%7}, {%8,%9}, {%0,%1,%2,%3};"
                 : "+f"(c[0]), "+f"(c[1]), "+f"(c[2]), "+f"(c[3])
                 : "r"(a[0]), "r"(a[1]), "r"(a[2]), "r"(a[3]), "r"(b[0]), "r"(b[1]));
}

// padded smem strides (bytes) — conflict-free ldmatrix phases
#define A_STRIDE 80      // 32 halves + 16B pad : banks 20r mod 32 distinct
#define B_STRIDE 272     // 128 halves + 16B pad: banks 4k mod 32 distinct
#define A_BYTES  (128 * A_STRIDE)   // 10240
#define B_BYTES  (32 * B_STRIDE)    // 8704

// ---------------- routing ----------------
__global__ void k_zero_out(float* out) {
    int i = blockIdx.x * 256 + threadIdx.x;
    if (i < T_TOK * DM) out[i] = 0.0f;
    if (blockIdx.x == 0 && threadIdx.x < N_EXP) { g_cnt[threadIdx.x] = 0; g_fill[threadIdx.x] = 0; }
}
__global__ void k_count(const int* __restrict__ eidx) {
    int s = blockIdx.x * 256 + threadIdx.x;
    if (s < NSLOT) atomicAdd(&g_cnt[eidx[s]], 1);
}
__global__ void k_scan() {
    if (threadIdx.x == 0) {
        int a = 0, nt = 0;
        for (int e = 0; e < N_EXP; e++) {
            g_off[e] = a;
            int c = g_cnt[e];
            for (int rb = 0; rb < c; rb += 128) g_tile[nt++] = make_int2(e, rb);
            a += c;
        }
        g_off[N_EXP] = a;
        g_ntiles = nt;
    }
}
__global__ void k_fill(const int* __restrict__ eidx, const float* __restrict__ rw) {
    int s = blockIdx.x * 256 + threadIdx.x;
    if (s < NSLOT) {
        int e = eidx[s];
        int p = g_off[e] + atomicAdd(&g_fill[e], 1);
        g_tok[p] = s / TOPK;
        g_wt[p]  = rw[s];
    }
}

// ---------------- fused fp32 -> fp16 convert (all 4 tensors) ----------------
#define NWEL ((size_t)N_EXP * DM * DE)    // 18874368
#define NXEL ((size_t)T_TOK * DM)         // 3145728
#define CVT_TASKS ((3 * NWEL + NXEL) / 4) // 14942208
__global__ __launch_bounds__(256) void k_cvt_all(const float* __restrict__ wg,
                                                 const float* __restrict__ wu,
                                                 const float* __restrict__ wd,
                                                 const float* __restrict__ x) {
    size_t i = ((size_t)blockIdx.x * 256 + threadIdx.x) * 4;
    const float* s; __half* d;
    if (i < NWEL)            { s = wg; d = g_wgH; }
    else if (i < 2 * NWEL)   { s = wu; d = g_wuH; i -= NWEL; }
    else if (i < 3 * NWEL)   { s = wd; d = g_wdH; i -= 2 * NWEL; }
    else                     { s = x;  d = g_xH;  i -= 3 * NWEL; if (i >= NXEL) return; }
    float4 v = *(const float4*)(s + i);
    *(__half2*)(d + i)     = __floats2half2_rn(v.x, v.y);
    *(__half2*)(d + i + 2) = __floats2half2_rn(v.z, v.w);
}

// ===========================================================================
// GEMM1: h = silu(x Wg) * (x Wu) — fp16 mma.sync, 4-stage cp.async
// CTA 128x128x32, 8 warps (2x4), warp tile 64x32
// ===========================================================================
#define STG1 (A_BYTES + 2 * B_BYTES)   // 27648
#define S1_SMEM (4 * STG1)             // 110592
#define NS1 24                         // 768/32

__global__ __launch_bounds__(256) void k_mma1() {
    if (blockIdx.y >= (unsigned)g_ntiles) return;
    const int2 te = g_tile[blockIdx.y];
    const int e = te.x, row0 = te.y;
    const int cnt = g_cnt[e];
    const int base = g_off[e];
    const int col0 = blockIdx.x * 128;

    extern __shared__ char sm[];
    const uint32_t sa = smem_u32(sm);

    const int tid = threadIdx.x;
    const int wid = tid >> 5, lid = tid & 31;
    const int wm = wid >> 2, wn = wid & 3;
    const int g = lid >> 2, t = lid & 3;
    const int lidlo = lid & 15, lidhi = lid >> 4;

    uint32_t aoff[2], boff[2];
    const char* pA[2]; const char* pG[2]; const char* pU[2];
    #pragma unroll
    for (int j = 0; j < 2; j++) {
        int task = tid + 256 * j;
        int ar = task >> 2, ac = task & 3;
        int rr = row0 + ar;
        int idx = base + (rr < cnt ? rr : cnt - 1);
        pA[j] = (const char*)(g_xH + (size_t)g_tok[idx] * DM) + ac * 16;
        aoff[j] = (uint32_t)(ar * A_STRIDE + ac * 16);
        int br = task >> 4, bc = task & 15;
        pG[j] = (const char*)(g_wgH + ((size_t)e * DM + br) * DE + col0) + bc * 16;
        pU[j] = (const char*)(g_wuH + ((size_t)e * DM + br) * DE + col0) + bc * 16;
        boff[j] = (uint32_t)(br * B_STRIDE + bc * 16);
    }
    const size_t bAdv = (size_t)32 * DE * 2;

#define LOAD1(buf) do {                                                        \
        uint32_t ab = sa + (uint32_t)((buf) * STG1);                           \
        uint32_t gb = ab + A_BYTES, ub = gb + B_BYTES;                         \
        _Pragma("unroll") for (int j = 0; j < 2; j++) {                        \
            CP16(ab + aoff[j], pA[j]); pA[j] += 64;                            \
            CP16(gb + boff[j], pG[j]); CP16(ub + boff[j], pU[j]);              \
            pG[j] += bAdv; pU[j] += bAdv; } } while (0)

    float accG[4][4][4] = {}, accU[4][4][4] = {};

    LOAD1(0); CP_COMMIT();
    LOAD1(1); CP_COMMIT();
    LOAD1(2); CP_COMMIT();

    for (int s = 0; s < NS1; s++) {
        CP_WAIT2();
        __syncthreads();
        if (s + 3 < NS1) LOAD1((s + 3) & 3);
        CP_COMMIT();

        const uint32_t ab = sa + (uint32_t)((s & 3) * STG1);
        const uint32_t gb = ab + A_BYTES, ub = gb + B_BYTES;

        #pragma unroll
        for (int kst = 0; kst < 2; kst++) {
            uint32_t a[4][4], bg[4][2], bu[4][2];
            #pragma unroll
            for (int mi = 0; mi < 4; mi++) {
                uint32_t addr = ab + (uint32_t)((wm * 64 + mi * 16 + lidlo) * A_STRIDE
                                                + (kst * 16 + 8 * lidhi) * 2);
                LDSM_X4(a[mi][0], a[mi][1], a[mi][2], a[mi][3], addr);
            }
            #pragma unroll
            for (int nh = 0; nh < 2; nh++) {
                uint32_t co = (uint32_t)((wn * 32 + nh * 16 + 8 * lidhi) * 2);
                uint32_t ro = (uint32_t)((kst * 16 + lidlo) * B_STRIDE);
                LDSM_X4T(bg[2 * nh][0], bg[2 * nh][1], bg[2 * nh + 1][0], bg[2 * nh + 1][1],
                         gb + ro + co);
                LDSM_X4T(bu[2 * nh][0], bu[2 * nh][1], bu[2 * nh + 1][0], bu[2 * nh + 1][1],
                         ub + ro + co);
            }
            #pragma unroll
            for (int mi = 0; mi < 4; mi++)
                #pragma unroll
                for (int ni = 0; ni < 4; ni++) {
                    mma_f16(accG[mi][ni], a[mi], bg[ni]);
                    mma_f16(accU[mi][ni], a[mi], bu[ni]);
                }
        }
    }

    // ---- epilogue: silu(g)*u -> g_hH (fp16) ----
    #pragma unroll
    for (int mi = 0; mi < 4; mi++) {
        #pragma unroll
        for (int hh = 0; hh < 2; hh++) {
            int r = row0 + wm * 64 + mi * 16 + g + 8 * hh;
            if (r >= cnt) continue;
            __half* hrow = g_hH + (size_t)(base + r) * DE + col0;
            #pragma unroll
            for (int ni = 0; ni < 4; ni++) {
                int col = wn * 32 + ni * 8 + 2 * t;
                float gv0 = accG[mi][ni][2 * hh], gv1 = accG[mi][ni][2 * hh + 1];
                float uv0 = accU[mi][ni][2 * hh], uv1 = accU[mi][ni][2 * hh + 1];
                float h0 = gv0 * uv0 / (1.0f + __expf(-gv0));
                float h1 = gv1 * uv1 / (1.0f + __expf(-gv1));
                *(__half2*)(hrow + col) = __floats2half2_rn(h0, h1);
            }
        }
    }
}

// ===========================================================================
// GEMM2: out += (h Wd) * wt
// ===========================================================================
#define STG2 (A_BYTES + B_BYTES)    // 18944
#define S2_SMEM (4 * STG2)          // 75776
#define NS2 96                      // 3072/32

__global__ __launch_bounds__(256) void k_mma2(float* __restrict__ out) {
    if (blockIdx.y >= (unsigned)g_ntiles) return;
    const int2 te = g_tile[blockIdx.y];
    const int e = te.x, row0 = te.y;
    const int cnt = g_cnt[e];
    const int base = g_off[e];
    const int col0 = blockIdx.x * 128;

    extern __shared__ char sm[];
    const uint32_t sa = smem_u32(sm);

    const int tid = threadIdx.x;
    const int wid = tid >> 5, lid = tid & 31;
    const int wm = wid >> 2, wn = wid & 3;
    const int g = lid >> 2, t = lid & 3;
    const int lidlo = lid & 15, lidhi = lid >> 4;

    uint32_t aoff[2], boff[2];
    const char* pA[2]; const char* pB[2];
    #pragma unroll
    for (int j = 0; j < 2; j++) {
        int task = tid + 256 * j;
        int ar = task >> 2, ac = task & 3;
        pA[j] = (const char*)(g_hH + (size_t)(base + row0 + ar) * DE) + ac * 16;
        aoff[j] = (uint32_t)(ar * A_STRIDE + ac * 16);
        int br = task >> 4, bc = task & 15;
        pB[j] = (const char*)(g_wdH + ((size_t)e * DE + br) * DM + col0) + bc * 16;
        boff[j] = (uint32_t)(br * B_STRIDE + bc * 16);
    }
    const size_t bAdv = (size_t)32 * DM * 2;

#define LOAD2(buf) do {                                                        \
        uint32_t ab = sa + (uint32_t)((buf) * STG2);                           \
        uint32_t bb = ab + A_BYTES;                                            \
        _Pragma("unroll") for (int j = 0; j < 2; j++) {                        \
            CP16(ab + aoff[j], pA[j]); pA[j] += 64;                            \
            CP16(bb + boff[j], pB[j]); pB[j] += bAdv; } } while (0)

    float acc[4][4][4] = {};

    LOAD2(0); CP_COMMIT();
    LOAD2(1); CP_COMMIT();
    LOAD2(2); CP_COMMIT();

    for (int s = 0; s < NS2; s++) {
        CP_WAIT2();
        __syncthreads();
        if (s + 3 < NS2) LOAD2((s + 3) & 3);
        CP_COMMIT();

        const uint32_t ab = sa + (uint32_t)((s & 3) * STG2);
        const uint32_t bb = ab + A_BYTES;

        #pragma unroll
        for (int kst = 0; kst < 2; kst++) {
            uint32_t a[4][4], bf[4][2];
            #pragma unroll
            for (int mi = 0; mi < 4; mi++) {
                uint32_t addr = ab + (uint32_t)((wm * 64 + mi * 16 + lidlo) * A_STRIDE
                                                + (kst * 16 + 8 * lidhi) * 2);
                LDSM_X4(a[mi][0], a[mi][1], a[mi][2], a[mi][3], addr);
            }
            #pragma unroll
            for (int nh = 0; nh < 2; nh++) {
                uint32_t co = (uint32_t)((wn * 32 + nh * 16 + 8 * lidhi) * 2);
                uint32_t ro = (uint32_t)((kst * 16 + lidlo) * B_STRIDE);
                LDSM_X4T(bf[2 * nh][0], bf[2 * nh][1], bf[2 * nh + 1][0], bf[2 * nh + 1][1],
                         bb + ro + co);
            }
            #pragma unroll
            for (int mi = 0; mi < 4; mi++)
                #pragma unroll
                for (int ni = 0; ni < 4; ni++)
                    mma_f16(acc[mi][ni], a[mi], bf[ni]);
        }
    }

    #pragma unroll
    for (int mi = 0; mi < 4; mi++) {
        #pragma unroll
        for (int hh = 0; hh < 2; hh++) {
            int r = row0 + wm * 64 + mi * 16 + g + 8 * hh;
            if (r >= cnt) continue;
            float w = g_wt[base + r];
            float* orow = out + (size_t)g_tok[base + r] * DM + col0;
            #pragma unroll
            for (int ni = 0; ni < 4; ni++) {
                int col = wn * 32 + ni * 8 + 2 * t;
                atomicAdd(&orow[col],     acc[mi][ni][2 * hh]     * w);
                atomicAdd(&orow[col + 1], acc[mi][ni][2 * hh + 1] * w);
            }
        }
    }
}

// ---------------------------------------------------------------------------
extern "C" void kernel_launch(void* const* d_in, const int* in_sizes, int n_in,
                              void* d_out, int out_size) {
    const float* x  = (const float*)d_in[0];
    const float* rw = (const float*)d_in[1];
    const float* wg = (const float*)d_in[2];
    const float* wu = (const float*)d_in[3];
    const float* wd = (const float*)d_in[4];
    const int*   ei = (const int*)d_in[5];
    float* out = (float*)d_out;

    static bool attr_done = false;
    if (!attr_done) {
        cudaFuncSetAttribute(k_mma1, cudaFuncAttributeMaxDynamicSharedMemorySize, S1_SMEM);
        cudaFuncSetAttribute(k_mma2, cudaFuncAttributeMaxDynamicSharedMemorySize, S2_SMEM);
        attr_done = true;
    }

    k_zero_out<<<(T_TOK * DM + 255) / 256, 256>>>(out);
    k_count<<<NSLOT / 256, 256>>>(ei);
    k_scan<<<1, 32>>>();
    k_fill<<<NSLOT / 256, 256>>>(ei, rw);

    k_cvt_all<<<(int)((CVT_TASKS + 255) / 256), 256>>>(wg, wu, wd, x);

    dim3 g1(DE / 128, MAXTILE);   // 24 x 72
    k_mma1<<<g1, 256, S1_SMEM>>>();

    dim3 g2(DM / 128, MAXTILE);   // 6 x 72
    k_mma2<<<g2, 256, S2_SMEM>>>(out);
}